// round 8
// baseline (speedup 1.0000x reference)
#include <cuda_runtime.h>
#include <cuda_bf16.h>
#include <math.h>

#define T_TOK 2048
#define D_DIM 1024
#define F_DIM 2048
#define NE 8

// ---- scratch: referenced ONLY inside device code (never passed as kernel args) ----
// bf16 hi/lo planes for everything the GEMMs touch.
__device__ __nv_bfloat16 g_Wgh[(size_t)NE * D_DIM * F_DIM], g_Wgl[(size_t)NE * D_DIM * F_DIM];
__device__ __nv_bfloat16 g_Wuh[(size_t)NE * D_DIM * F_DIM], g_Wul[(size_t)NE * D_DIM * F_DIM];
__device__ __nv_bfloat16 g_Wdh[(size_t)NE * F_DIM * D_DIM], g_Wdl[(size_t)NE * F_DIM * D_DIM];
__device__ __nv_bfloat16 g_sWgh[(size_t)D_DIM * F_DIM], g_sWgl[(size_t)D_DIM * F_DIM];
__device__ __nv_bfloat16 g_sWuh[(size_t)D_DIM * F_DIM], g_sWul[(size_t)D_DIM * F_DIM];
__device__ __nv_bfloat16 g_sWdh[(size_t)F_DIM * D_DIM], g_sWdl[(size_t)F_DIM * D_DIM];
__device__ __nv_bfloat16 g_Xh [(size_t)T_TOK * D_DIM], g_Xl [(size_t)T_TOK * D_DIM]; // hidden, token order
__device__ __nv_bfloat16 g_Xeh[(size_t)T_TOK * D_DIM], g_Xel[(size_t)T_TOK * D_DIM]; // scaled, grouped order
__device__ __nv_bfloat16 g_Hh [(size_t)T_TOK * F_DIM], g_Hl [(size_t)T_TOK * F_DIM]; // shared H planes
__device__ __nv_bfloat16 g_H2h[(size_t)T_TOK * F_DIM], g_H2l[(size_t)T_TOK * F_DIM]; // routed H planes
__device__ float g_O2[(size_t)T_TOK * D_DIM];
__device__ int   g_tok_e[T_TOK];
__device__ float g_tok_s[T_TOK];
__device__ int   g_row[T_TOK];                  // token -> grouped row
__device__ int   g_order[T_TOK];                // grouped row -> token
__device__ int   g_offs[NE + 1];

__device__ __forceinline__ float silu_f(float x) { return x / (1.0f + expf(-x)); }

__device__ __forceinline__ void split2(float x0, float x1, unsigned &hi, unsigned &lo) {
    __nv_bfloat16 h0 = __float2bfloat16_rn(x0), h1 = __float2bfloat16_rn(x1);
    hi = (unsigned)__bfloat16_as_ushort(h0) | ((unsigned)__bfloat16_as_ushort(h1) << 16);
    float r0 = x0 - __bfloat162float(h0), r1 = x1 - __bfloat162float(h1);
    lo = (unsigned)__bfloat16_as_ushort(__float2bfloat16_rn(r0))
       | ((unsigned)__bfloat16_as_ushort(__float2bfloat16_rn(r1)) << 16);
}

__device__ __forceinline__ void ldsm4(unsigned r[4], const void* p) {
    unsigned a = (unsigned)__cvta_generic_to_shared(p);
    asm volatile("ldmatrix.sync.aligned.m8n8.x4.shared.b16 {%0,%1,%2,%3}, [%4];"
                 : "=r"(r[0]), "=r"(r[1]), "=r"(r[2]), "=r"(r[3]) : "r"(a));
}
__device__ __forceinline__ void ldsm4t(unsigned r[4], const void* p) {
    unsigned a = (unsigned)__cvta_generic_to_shared(p);
    asm volatile("ldmatrix.sync.aligned.m8n8.x4.trans.shared.b16 {%0,%1,%2,%3}, [%4];"
                 : "=r"(r[0]), "=r"(r[1]), "=r"(r[2]), "=r"(r[3]) : "r"(a));
}
__device__ __forceinline__ void mma_bf16(float c[4], const unsigned a[4], unsigned b0, unsigned b1) {
    asm volatile(
        "mma.sync.aligned.m16n8k16.row.col.f32.bf16.bf16.f32 "
        "{%0,%1,%2,%3}, {%4,%5,%6,%7}, {%8,%9}, {%0,%1,%2,%3};"
        : "+f"(c[0]), "+f"(c[1]), "+f"(c[2]), "+f"(c[3])
        : "r"(a[0]), "r"(a[1]), "r"(a[2]), "r"(a[3]), "r"(b0), "r"(b1));
}

// ---------------- weight conversion: fp32 -> bf16 hi/lo planes ----------------
__global__ void conv_kernel(const float* __restrict__ src, int which, int n4) {
    __nv_bfloat16 *dh, *dl;
    switch (which) {
        case 0: dh = g_Wgh;  dl = g_Wgl;  break;
        case 1: dh = g_Wuh;  dl = g_Wul;  break;
        case 2: dh = g_Wdh;  dl = g_Wdl;  break;
        case 3: dh = g_sWgh; dl = g_sWgl; break;
        case 4: dh = g_sWuh; dl = g_sWul; break;
        default: dh = g_sWdh; dl = g_sWdl; break;
    }
    for (size_t i = (size_t)blockIdx.x * blockDim.x + threadIdx.x; i < (size_t)n4;
         i += (size_t)gridDim.x * blockDim.x) {
        float4 v = ((const float4*)src)[i];
        unsigned h0, l0, h1, l1;
        split2(v.x, v.y, h0, l0); split2(v.z, v.w, h1, l1);
        ((unsigned*)dh)[2 * i] = h0; ((unsigned*)dh)[2 * i + 1] = h1;
        ((unsigned*)dl)[2 * i] = l0; ((unsigned*)dl)[2 * i + 1] = l1;
    }
}

// ---------------- router: one block per token, coalesced, deterministic ----------------
__global__ void router_kernel(const float* __restrict__ x, const float* __restrict__ rw) {
    __shared__ float red[256][NE + 1];
    int t = blockIdx.x, tid = threadIdx.x;
    float4 xa = ((const float4*)(x + (size_t)t * D_DIM))[tid];
#pragma unroll
    for (int e = 0; e < NE; e++) {
        float4 wv = ((const float4*)(rw + (size_t)e * D_DIM))[tid];
        red[tid][e] = xa.x * wv.x + xa.y * wv.y + xa.z * wv.z + xa.w * wv.w;
    }
    __syncthreads();
    for (int s = 128; s > 0; s >>= 1) {
        if (tid < s)
#pragma unroll
            for (int e = 0; e < NE; e++) red[tid][e] += red[tid + s][e];
        __syncthreads();
    }
    if (tid == 0) {
        float bv = red[0][0]; int be = 0;
#pragma unroll
        for (int e = 1; e < NE; e++) if (red[0][e] > bv) { bv = red[0][e]; be = e; }
        g_tok_e[t] = be;
        g_tok_s[t] = 1.0f / (1.0f + expf(-bv));
    }
}

// ---------------- stable rank + offsets (smem-cached brute force, deterministic) ----------------
__global__ void rank_kernel() {
    __shared__ int s_e[T_TOK];
    int tid = threadIdx.x;
    for (int i = tid; i < T_TOK; i += 256) s_e[i] = g_tok_e[i];
    __syncthreads();
    int t = blockIdx.x * 256 + tid;
    int e = s_e[t];
    int r = 0;
#pragma unroll 4
    for (int u = 0; u < T_TOK; u++) {
        int eu = s_e[u];
        r += (eu < e) || (eu == e && u < t);
    }
    g_row[t] = r;
    g_order[r] = t;
}

__global__ void offs_kernel() {
    __shared__ int s_e[T_TOK];
    int tid = threadIdx.x;
    for (int i = tid; i < T_TOK; i += 256) s_e[i] = g_tok_e[i];
    __syncthreads();
    if (tid <= NE) {
        int c = 0;
#pragma unroll 4
        for (int u = 0; u < T_TOK; u++) c += (s_e[u] < tid);
        g_offs[tid] = c;
    }
}

// ---------------- scatter+convert: hidden -> X planes (token order) + scaled Xe planes (grouped) ----------------
__global__ void scatter_convert(const float* __restrict__ x) {
    int t = blockIdx.x, tid = threadIdx.x;
    int r = g_row[t];
    float s = g_tok_s[t];
    float4 v = ((const float4*)(x + (size_t)t * D_DIM))[tid];
    unsigned h0, l0, h1, l1;
    split2(v.x, v.y, h0, l0); split2(v.z, v.w, h1, l1);
    size_t o = ((size_t)t * D_DIM) / 2 + tid * 2;
    ((unsigned*)g_Xh)[o] = h0; ((unsigned*)g_Xh)[o + 1] = h1;
    ((unsigned*)g_Xl)[o] = l0; ((unsigned*)g_Xl)[o + 1] = l1;
    split2(v.x * s, v.y * s, h0, l0); split2(v.z * s, v.w * s, h1, l1);
    size_t o2 = ((size_t)r * D_DIM) / 2 + tid * 2;
    ((unsigned*)g_Xeh)[o2] = h0; ((unsigned*)g_Xeh)[o2 + 1] = h1;
    ((unsigned*)g_Xel)[o2] = l0; ((unsigned*)g_Xel)[o2 + 1] = l1;
}

// ================= split-bf16 tensor-core gate+up GEMM (all-bf16 staging) =================
// Block 128m x 64n, BK=16, 8 warps 4(m) x 2(n); z=0 shared -> H planes, z=1..NE routed -> H2 planes.
__global__ void __launch_bounds__(256, 2)
gemm_gateup_all() {
    const int BM = 128, BK = 16;
    const int LDA = 24, LDB = 72;
    const int K = D_DIM, N = F_DIM;

    int z = blockIdx.z;
    bool routed = (z > 0);
    int e = z - 1;
    int seg_start = 0, seg_rows = T_TOK;
    const __nv_bfloat16 *Ah, *Al, *Gh, *Gl, *Uh, *Ul;
    __nv_bfloat16 *Hh, *Hl;
    if (routed) {
        seg_start = g_offs[e]; seg_rows = g_offs[e + 1] - seg_start;
        Ah = g_Xeh; Al = g_Xel;
        size_t wo = (size_t)e * D_DIM * F_DIM;
        Gh = g_Wgh + wo; Gl = g_Wgl + wo; Uh = g_Wuh + wo; Ul = g_Wul + wo;
        Hh = g_H2h; Hl = g_H2l;
    } else {
        Ah = g_Xh; Al = g_Xl;
        Gh = g_sWgh; Gl = g_sWgl; Uh = g_sWuh; Ul = g_sWul;
        Hh = g_Hh; Hl = g_Hl;
    }
    int row0 = blockIdx.y * BM;
    if (row0 >= seg_rows) return;
    int col0 = blockIdx.x * 64;

    __shared__ __align__(16) __nv_bfloat16 sAh[2][BM * LDA], sAl[2][BM * LDA];
    __shared__ __align__(16) __nv_bfloat16 sGh[2][BK * LDB], sGl[2][BK * LDB];
    __shared__ __align__(16) __nv_bfloat16 sUh[2][BK * LDB], sUl[2][BK * LDB];

    int tid = threadIdx.x, lane = tid & 31, wid = tid >> 5;
    int wm = wid & 3, wn = wid >> 2;

    // A staging: thread -> (row, 8-elem chunk); 128 rows x 2 chunks = 256
    int arow = tid >> 1, ak8 = (tid & 1) * 8;
    bool av = (row0 + arow) < seg_rows;
    const __nv_bfloat16* aph = Ah + (size_t)(seg_start + row0 + (av ? arow : 0)) * K + ak8;
    const __nv_bfloat16* apl = Al + (size_t)(seg_start + row0 + (av ? arow : 0)) * K + ak8;
    // B staging: 4 planes (gh,gl,uh,ul); 64 threads/plane; each thread rows brow & brow+8
    int bpl = tid >> 6, bsub = tid & 63;
    int brow = bsub >> 3, bch = (bsub & 7) * 8;
    const __nv_bfloat16* bsrc = (bpl == 0) ? Gh : (bpl == 1) ? Gl : (bpl == 2) ? Uh : Ul;
    const __nv_bfloat16* bp0 = bsrc + (size_t)brow * N + col0 + bch;
    const __nv_bfloat16* bp1 = bsrc + (size_t)(brow + 8) * N + col0 + bch;

    float accg[2][4][4] = {}, accu[2][4][4] = {};

    auto stage = [&](int buf, uint4 a_h, uint4 a_l, uint4 b0, uint4 b1) {
        *(uint4*)&sAh[buf][arow * LDA + ak8] = a_h;
        *(uint4*)&sAl[buf][arow * LDA + ak8] = a_l;
        __nv_bfloat16* sB = (bpl == 0) ? &sGh[buf][0] : (bpl == 1) ? &sGl[buf][0]
                           : (bpl == 2) ? &sUh[buf][0] : &sUl[buf][0];
        *(uint4*)&sB[brow * LDB + bch] = b0;
        *(uint4*)&sB[(brow + 8) * LDB + bch] = b1;
    };

    auto compute = [&](int buf) {
        unsigned ah[2][4], al[2][4];
#pragma unroll
        for (int mt = 0; mt < 2; mt++) {
            int r = wm * 32 + mt * 16 + (lane & 15);
            int kk = (lane >> 4) * 8;
            ldsm4(ah[mt], &sAh[buf][r * LDA + kk]);
            ldsm4(al[mt], &sAl[buf][r * LDA + kk]);
        }
#pragma unroll
        for (int h = 0; h < 2; h++) {
            int krow = lane & 15;
            int nof = wn * 32 + h * 16 + (lane >> 4) * 8;
            unsigned gh[4], gl[4], uh[4], ul[4];
            ldsm4t(gh, &sGh[buf][krow * LDB + nof]);
            ldsm4t(gl, &sGl[buf][krow * LDB + nof]);
            ldsm4t(uh, &sUh[buf][krow * LDB + nof]);
            ldsm4t(ul, &sUl[buf][krow * LDB + nof]);
#pragma unroll
            for (int mt = 0; mt < 2; mt++)
#pragma unroll
                for (int nn = 0; nn < 2; nn++) {
                    float* cg = accg[mt][h * 2 + nn];
                    float* cu = accu[mt][h * 2 + nn];
                    mma_bf16(cg, ah[mt], gh[2*nn], gh[2*nn+1]);
                    mma_bf16(cg, ah[mt], gl[2*nn], gl[2*nn+1]);
                    mma_bf16(cg, al[mt], gh[2*nn], gh[2*nn+1]);
                    mma_bf16(cu, ah[mt], uh[2*nn], uh[2*nn+1]);
                    mma_bf16(cu, ah[mt], ul[2*nn], ul[2*nn+1]);
                    mma_bf16(cu, al[mt], uh[2*nn], uh[2*nn+1]);
                }
        }
    };

    const uint4 z4 = make_uint4(0, 0, 0, 0);
    const int nT = K / BK;
    stage(0, av ? *(const uint4*)aph : z4, av ? *(const uint4*)apl : z4,
          *(const uint4*)bp0, *(const uint4*)bp1);
    __syncthreads();

    for (int t = 0; t < nT - 1; t++) {
        int buf = t & 1;
        uint4 nah = av ? *(const uint4*)(aph + (t + 1) * BK) : z4;
        uint4 nal = av ? *(const uint4*)(apl + (t + 1) * BK) : z4;
        uint4 nb0 = *(const uint4*)(bp0 + (size_t)(t + 1) * BK * N);
        uint4 nb1 = *(const uint4*)(bp1 + (size_t)(t + 1) * BK * N);
        compute(buf);
        stage(buf ^ 1, nah, nal, nb0, nb1);
        __syncthreads();
    }
    compute((nT - 1) & 1);

    // epilogue: H = silu(g)*u, split to bf16 hi/lo planes
    __nv_bfloat16* Hhs = Hh + (size_t)seg_start * N;
    __nv_bfloat16* Hls = Hl + (size_t)seg_start * N;
#pragma unroll
    for (int mt = 0; mt < 2; mt++)
#pragma unroll
        for (int nn = 0; nn < 4; nn++) {
            int r0 = row0 + wm * 32 + mt * 16 + (lane >> 2);
            int c = col0 + wn * 32 + nn * 8 + (lane & 3) * 2;
            float* cg = accg[mt][nn]; float* cu = accu[mt][nn];
            if (r0 < seg_rows) {
                unsigned h, l;
                split2(silu_f(cg[0]) * cu[0], silu_f(cg[1]) * cu[1], h, l);
                ((unsigned*)Hhs)[((size_t)r0 * N + c) >> 1] = h;
                ((unsigned*)Hls)[((size_t)r0 * N + c) >> 1] = l;
            }
            int r1 = r0 + 8;
            if (r1 < seg_rows) {
                unsigned h, l;
                split2(silu_f(cg[2]) * cu[2], silu_f(cg[3]) * cu[3], h, l);
                ((unsigned*)Hhs)[((size_t)r1 * N + c) >> 1] = h;
                ((unsigned*)Hls)[((size_t)r1 * N + c) >> 1] = l;
            }
        }
}

// ================= split-bf16 tensor-core down GEMM (all-bf16 staging) =================
// Block 128m x 128n, BK=16; z=0: H planes @ sWd -> out ; z=1..NE: H2 seg @ Wd[e] -> g_O2 (scattered).
__global__ void __launch_bounds__(256, 2)
gemm_down_all(float* __restrict__ out) {
    const int BM = 128, BK = 16;
    const int LDA = 24, LDB = 136;
    const int K = F_DIM, N = D_DIM;

    int z = blockIdx.z;
    bool routed = (z > 0);
    int e = z - 1;
    int seg_start = 0, seg_rows = T_TOK;
    const __nv_bfloat16 *Ah, *Al, *Bh, *Bl;
    if (routed) {
        seg_start = g_offs[e]; seg_rows = g_offs[e + 1] - seg_start;
        Ah = g_H2h; Al = g_H2l;
        size_t wo = (size_t)e * F_DIM * D_DIM;
        Bh = g_Wdh + wo; Bl = g_Wdl + wo;
    } else {
        Ah = g_Hh; Al = g_Hl; Bh = g_sWdh; Bl = g_sWdl;
    }
    int row0 = blockIdx.y * BM;
    if (row0 >= seg_rows) return;
    int col0 = blockIdx.x * 128;

    __shared__ __align__(16) __nv_bfloat16 sAh[2][BM * LDA], sAl[2][BM * LDA];
    __shared__ __align__(16) __nv_bfloat16 sBh[2][BK * LDB], sBl[2][BK * LDB];

    int tid = threadIdx.x, lane = tid & 31, wid = tid >> 5;
    int wm = wid & 3, wn = wid >> 2;

    int arow = tid >> 1, ak8 = (tid & 1) * 8;
    bool av = (row0 + arow) < seg_rows;
    const __nv_bfloat16* aph = Ah + (size_t)(seg_start + row0 + (av ? arow : 0)) * K + ak8;
    const __nv_bfloat16* apl = Al + (size_t)(seg_start + row0 + (av ? arow : 0)) * K + ak8;
    // B: 2 planes; 128 threads/plane; each thread rows brow & brow+8, 16 chunks
    int bpl = tid >> 7, bsub = tid & 127;
    int brow = bsub >> 4, bch = (bsub & 15) * 8;
    const __nv_bfloat16* bsrc = bpl ? Bl : Bh;
    const __nv_bfloat16* bp0 = bsrc + (size_t)brow * N + col0 + bch;
    const __nv_bfloat16* bp1 = bsrc + (size_t)(brow + 8) * N + col0 + bch;

    float acc[2][8][4] = {};

    auto stage = [&](int buf, uint4 a_h, uint4 a_l, uint4 b0, uint4 b1) {
        *(uint4*)&sAh[buf][arow * LDA + ak8] = a_h;
        *(uint4*)&sAl[buf][arow * LDA + ak8] = a_l;
        __nv_bfloat16* sB = bpl ? &sBl[buf][0] : &sBh[buf][0];
        *(uint4*)&sB[brow * LDB + bch] = b0;
        *(uint4*)&sB[(brow + 8) * LDB + bch] = b1;
    };

    auto compute = [&](int buf) {
        unsigned ah[2][4], al[2][4];
#pragma unroll
        for (int mt = 0; mt < 2; mt++) {
            int r = wm * 32 + mt * 16 + (lane & 15);
            int kk = (lane >> 4) * 8;
            ldsm4(ah[mt], &sAh[buf][r * LDA + kk]);
            ldsm4(al[mt], &sAl[buf][r * LDA + kk]);
        }
#pragma unroll
        for (int h = 0; h < 4; h++) {
            int krow = lane & 15;
            int nof = wn * 64 + h * 16 + (lane >> 4) * 8;
            unsigned bh[4], bl[4];
            ldsm4t(bh, &sBh[buf][krow * LDB + nof]);
            ldsm4t(bl, &sBl[buf][krow * LDB + nof]);
#pragma unroll
            for (int mt = 0; mt < 2; mt++)
#pragma unroll
                for (int nn = 0; nn < 2; nn++) {
                    float* c = acc[mt][h * 2 + nn];
                    mma_bf16(c, ah[mt], bh[2*nn], bh[2*nn+1]);
                    mma_bf16(c, ah[mt], bl[2*nn], bl[2*nn+1]);
                    mma_bf16(c, al[mt], bh[2*nn], bh[2*nn+1]);
                }
        }
    };

    const uint4 z4 = make_uint4(0, 0, 0, 0);
    const int nT = K / BK;
    stage(0, av ? *(const uint4*)aph : z4, av ? *(const uint4*)apl : z4,
          *(const uint4*)bp0, *(const uint4*)bp1);
    __syncthreads();

    for (int t = 0; t < nT - 1; t++) {
        int buf = t & 1;
        uint4 nah = av ? *(const uint4*)(aph + (t + 1) * BK) : z4;
        uint4 nal = av ? *(const uint4*)(apl + (t + 1) * BK) : z4;
        uint4 nb0 = *(const uint4*)(bp0 + (size_t)(t + 1) * BK * N);
        uint4 nb1 = *(const uint4*)(bp1 + (size_t)(t + 1) * BK * N);
        compute(buf);
        stage(buf ^ 1, nah, nal, nb0, nb1);
        __syncthreads();
    }
    compute((nT - 1) & 1);

#pragma unroll
    for (int mt = 0; mt < 2; mt++) {
        int rb0 = row0 + wm * 32 + mt * 16 + (lane >> 2);
        int rb1 = rb0 + 8;
        int tok0 = -1, tok1 = -1;
        if (rb0 < seg_rows) tok0 = routed ? g_order[seg_start + rb0] : rb0;
        if (rb1 < seg_rows) tok1 = routed ? g_order[seg_start + rb1] : rb1;
        float* dst = routed ? g_O2 : out;
#pragma unroll
        for (int nn = 0; nn < 8; nn++) {
            int c = col0 + wn * 64 + nn * 8 + (lane & 3) * 2;
            float* cc = acc[mt][nn];
            if (tok0 >= 0) { float2 v = { cc[0], cc[1] }; *(float2*)&dst[(size_t)tok0 * N + c] = v; }
            if (tok1 >= 0) { float2 v = { cc[2], cc[3] }; *(float2*)&dst[(size_t)tok1 * N + c] = v; }
        }
    }
}

// ---------------- final add: out += g_O2 ----------------
__global__ void add_kernel(float* __restrict__ out) {
    size_t i = (size_t)blockIdx.x * 256 + threadIdx.x;
    float4 v = ((float4*)out)[i];
    float4 w = ((const float4*)g_O2)[i];
    v.x += w.x; v.y += w.y; v.z += w.z; v.w += w.w;
    ((float4*)out)[i] = v;
}

extern "C" void kernel_launch(void* const* d_in, const int* in_sizes, int n_in,
                              void* d_out, int out_size) {
    const float* hidden   = (const float*)d_in[0];
    const float* router_w = (const float*)d_in[1];
    const float* w_gate   = (const float*)d_in[2];
    const float* w_up     = (const float*)d_in[3];
    const float* w_down   = (const float*)d_in[4];
    const float* ws_gate  = (const float*)d_in[5];
    const float* ws_up    = (const float*)d_in[6];
    const float* ws_down  = (const float*)d_in[7];
    float* out = (float*)d_out;

    const int RW4 = NE * D_DIM * F_DIM / 4;      // routed weight float4 count
    const int SW4 = D_DIM * F_DIM / 4;           // shared weight float4 count

    // weight conversion (independent of routing)
    conv_kernel<<<2048, 256>>>(w_gate,  0, RW4);
    conv_kernel<<<2048, 256>>>(w_up,    1, RW4);
    conv_kernel<<<2048, 256>>>(w_down,  2, RW4);
    conv_kernel<<<512,  256>>>(ws_gate, 3, SW4);
    conv_kernel<<<512,  256>>>(ws_up,   4, SW4);
    conv_kernel<<<512,  256>>>(ws_down, 5, SW4);

    // routing metadata
    router_kernel<<<T_TOK, 256>>>(hidden, router_w);
    rank_kernel<<<T_TOK / 256, 256>>>();
    offs_kernel<<<1, 256>>>();
    scatter_convert<<<T_TOK, 256>>>(hidden);

    // GEMMs
    dim3 gridGU(F_DIM / 64, T_TOK / 128, NE + 1);
    gemm_gateup_all<<<gridGU, 256>>>();
    dim3 gridDN(D_DIM / 128, T_TOK / 128, NE + 1);
    gemm_down_all<<<gridDN, 256>>>(out);
    add_kernel<<<(T_TOK * D_DIM / 4) / 256, 256>>>(out);

    (void)in_sizes; (void)n_in; (void)out_size;
}

// round 9
// speedup vs baseline: 1.1402x; 1.1402x over previous
#include <cuda_runtime.h>
#include <cuda_bf16.h>
#include <math.h>

#define T_TOK 2048
#define D_DIM 1024
#define F_DIM 2048
#define NE 8

// ---- scratch: referenced ONLY inside device code ----
__device__ __nv_bfloat16 g_sWgh[(size_t)D_DIM * F_DIM], g_sWgl[(size_t)D_DIM * F_DIM];
__device__ __nv_bfloat16 g_sWuh[(size_t)D_DIM * F_DIM], g_sWul[(size_t)D_DIM * F_DIM];
__device__ __nv_bfloat16 g_sWdh[(size_t)F_DIM * D_DIM], g_sWdl[(size_t)F_DIM * D_DIM];
__device__ __nv_bfloat16 g_Xh [(size_t)T_TOK * D_DIM], g_Xl [(size_t)T_TOK * D_DIM]; // hidden planes (token order)
__device__ __nv_bfloat16 g_Xeh[(size_t)T_TOK * D_DIM], g_Xel[(size_t)T_TOK * D_DIM]; // scaled planes (grouped)
__device__ __nv_bfloat16 g_Hh [(size_t)T_TOK * F_DIM], g_Hl [(size_t)T_TOK * F_DIM]; // shared H planes
__device__ __nv_bfloat16 g_H2h[(size_t)T_TOK * F_DIM], g_H2l[(size_t)T_TOK * F_DIM]; // routed H planes
__device__ float g_O2[(size_t)T_TOK * D_DIM];
__device__ int   g_tok_e[T_TOK];
__device__ float g_tok_s[T_TOK];
__device__ int   g_row[T_TOK];
__device__ int   g_order[T_TOK];
__device__ int   g_offs[NE + 1];

__device__ __forceinline__ float silu_f(float x) { return x / (1.0f + expf(-x)); }

__device__ __forceinline__ void split2(float x0, float x1, unsigned &hi, unsigned &lo) {
    __nv_bfloat16 h0 = __float2bfloat16_rn(x0), h1 = __float2bfloat16_rn(x1);
    hi = (unsigned)__bfloat16_as_ushort(h0) | ((unsigned)__bfloat16_as_ushort(h1) << 16);
    float r0 = x0 - __bfloat162float(h0), r1 = x1 - __bfloat162float(h1);
    lo = (unsigned)__bfloat16_as_ushort(__float2bfloat16_rn(r0))
       | ((unsigned)__bfloat16_as_ushort(__float2bfloat16_rn(r1)) << 16);
}

__device__ __forceinline__ void cpa16(void* smem, const void* gmem) {
    unsigned s = (unsigned)__cvta_generic_to_shared(smem);
    asm volatile("cp.async.cg.shared.global [%0], [%1], 16;" :: "r"(s), "l"(gmem));
}
__device__ __forceinline__ void cpa_commit() { asm volatile("cp.async.commit_group;"); }
__device__ __forceinline__ void cpa_wait_all() { asm volatile("cp.async.wait_group 0;"); }

__device__ __forceinline__ void ldsm4(unsigned r[4], const void* p) {
    unsigned a = (unsigned)__cvta_generic_to_shared(p);
    asm volatile("ldmatrix.sync.aligned.m8n8.x4.shared.b16 {%0,%1,%2,%3}, [%4];"
                 : "=r"(r[0]), "=r"(r[1]), "=r"(r[2]), "=r"(r[3]) : "r"(a));
}
__device__ __forceinline__ void ldsm4t(unsigned r[4], const void* p) {
    unsigned a = (unsigned)__cvta_generic_to_shared(p);
    asm volatile("ldmatrix.sync.aligned.m8n8.x4.trans.shared.b16 {%0,%1,%2,%3}, [%4];"
                 : "=r"(r[0]), "=r"(r[1]), "=r"(r[2]), "=r"(r[3]) : "r"(a));
}
__device__ __forceinline__ void mma_bf16(float c[4], const unsigned a[4], unsigned b0, unsigned b1) {
    asm volatile(
        "mma.sync.aligned.m16n8k16.row.col.f32.bf16.bf16.f32 "
        "{%0,%1,%2,%3}, {%4,%5,%6,%7}, {%8,%9}, {%0,%1,%2,%3};"
        : "+f"(c[0]), "+f"(c[1]), "+f"(c[2]), "+f"(c[3])
        : "r"(a[0]), "r"(a[1]), "r"(a[2]), "r"(a[3]), "r"(b0), "r"(b1));
}

// ---------------- convert shared weights only (high reuse) ----------------
__global__ void conv_shared(const float* __restrict__ g, const float* __restrict__ u,
                            const float* __restrict__ d) {
    const int n4 = D_DIM * F_DIM / 4;
    for (int idx = blockIdx.x * 256 + threadIdx.x; idx < 3 * n4; idx += gridDim.x * 256) {
        int which = idx / n4, i = idx - which * n4;
        const float* src = (which == 0) ? g : (which == 1) ? u : d;
        __nv_bfloat16* dh = (which == 0) ? g_sWgh : (which == 1) ? g_sWuh : g_sWdh;
        __nv_bfloat16* dl = (which == 0) ? g_sWgl : (which == 1) ? g_sWul : g_sWdl;
        float4 v = ((const float4*)src)[i];
        unsigned h0, l0, h1, l1;
        split2(v.x, v.y, h0, l0); split2(v.z, v.w, h1, l1);
        ((unsigned*)dh)[2 * i] = h0; ((unsigned*)dh)[2 * i + 1] = h1;
        ((unsigned*)dl)[2 * i] = l0; ((unsigned*)dl)[2 * i + 1] = l1;
    }
}

// ---------------- router ----------------
__global__ void router_kernel(const float* __restrict__ x, const float* __restrict__ rw) {
    __shared__ float red[256][NE + 1];
    int t = blockIdx.x, tid = threadIdx.x;
    float4 xa = ((const float4*)(x + (size_t)t * D_DIM))[tid];
#pragma unroll
    for (int e = 0; e < NE; e++) {
        float4 wv = ((const float4*)(rw + (size_t)e * D_DIM))[tid];
        red[tid][e] = xa.x * wv.x + xa.y * wv.y + xa.z * wv.z + xa.w * wv.w;
    }
    __syncthreads();
    for (int s = 128; s > 0; s >>= 1) {
        if (tid < s)
#pragma unroll
            for (int e = 0; e < NE; e++) red[tid][e] += red[tid + s][e];
        __syncthreads();
    }
    if (tid == 0) {
        float bv = red[0][0]; int be = 0;
#pragma unroll
        for (int e = 1; e < NE; e++) if (red[0][e] > bv) { bv = red[0][e]; be = e; }
        g_tok_e[t] = be;
        g_tok_s[t] = 1.0f / (1.0f + expf(-bv));
    }
}

// ---------------- stable rank + offsets (merged) ----------------
__global__ void rank_kernel() {
    __shared__ int s_e[T_TOK];
    int tid = threadIdx.x;
    for (int i = tid; i < T_TOK; i += 256) s_e[i] = g_tok_e[i];
    __syncthreads();
    int t = blockIdx.x * 256 + tid;
    int e = s_e[t];
    int r = 0;
#pragma unroll 4
    for (int u = 0; u < T_TOK; u++) {
        int eu = s_e[u];
        r += (eu < e) || (eu == e && u < t);
    }
    g_row[t] = r;
    g_order[r] = t;
    if (blockIdx.x == 0 && tid <= NE) {
        int c = 0;
#pragma unroll 4
        for (int u = 0; u < T_TOK; u++) c += (s_e[u] < tid);
        g_offs[tid] = c;
    }
}

// ---------------- scatter+convert hidden ----------------
__global__ void scatter_convert(const float* __restrict__ x) {
    int t = blockIdx.x, tid = threadIdx.x;
    int r = g_row[t];
    float s = g_tok_s[t];
    float4 v = ((const float4*)(x + (size_t)t * D_DIM))[tid];
    unsigned h0, l0, h1, l1;
    split2(v.x, v.y, h0, l0); split2(v.z, v.w, h1, l1);
    size_t o = ((size_t)t * D_DIM) / 2 + tid * 2;
    ((unsigned*)g_Xh)[o] = h0; ((unsigned*)g_Xh)[o + 1] = h1;
    ((unsigned*)g_Xl)[o] = l0; ((unsigned*)g_Xl)[o + 1] = l1;
    split2(v.x * s, v.y * s, h0, l0); split2(v.z * s, v.w * s, h1, l1);
    size_t o2 = ((size_t)r * D_DIM) / 2 + tid * 2;
    ((unsigned*)g_Xeh)[o2] = h0; ((unsigned*)g_Xeh)[o2 + 1] = h1;
    ((unsigned*)g_Xel)[o2] = l0; ((unsigned*)g_Xel)[o2 + 1] = l1;
}

// ================= gate+up GEMM: cp.async planes for A (+B shared); in-kernel split for routed B =================
__global__ void __launch_bounds__(256, 2)
gemm_gateup_all(const float* __restrict__ w_gate, const float* __restrict__ w_up) {
    const int BM = 128, BK = 16;
    const int LDA = 24, LDB = 72;
    const int K = D_DIM, N = F_DIM;

    int z = blockIdx.z;
    bool routed = (z > 0);
    int e = z - 1;
    int seg_start = 0, seg_rows = T_TOK;
    const __nv_bfloat16 *Ah, *Al;
    __nv_bfloat16 *Hh, *Hl;
    const float *Gf = nullptr, *Uf = nullptr;                 // routed fp32 weights
    const __nv_bfloat16 *Gh = nullptr, *Gl = nullptr, *Uh = nullptr, *Ul = nullptr;
    if (routed) {
        seg_start = g_offs[e]; seg_rows = g_offs[e + 1] - seg_start;
        Ah = g_Xeh; Al = g_Xel;
        Gf = w_gate + (size_t)e * D_DIM * F_DIM;
        Uf = w_up   + (size_t)e * D_DIM * F_DIM;
        Hh = g_H2h; Hl = g_H2l;
    } else {
        Ah = g_Xh; Al = g_Xl;
        Gh = g_sWgh; Gl = g_sWgl; Uh = g_sWuh; Ul = g_sWul;
        Hh = g_Hh; Hl = g_Hl;
    }
    int row0 = blockIdx.y * BM;
    if (row0 >= seg_rows) return;
    int col0 = blockIdx.x * 64;

    __shared__ __align__(16) __nv_bfloat16 sAh[2][BM * LDA], sAl[2][BM * LDA];
    __shared__ __align__(16) __nv_bfloat16 sGh[2][BK * LDB], sGl[2][BK * LDB];
    __shared__ __align__(16) __nv_bfloat16 sUh[2][BK * LDB], sUl[2][BK * LDB];

    int tid = threadIdx.x, lane = tid & 31, wid = tid >> 5;
    int wm = wid & 3, wn = wid >> 2;

    // A staging (planes, clamped rows)
    int arow = tid >> 1, ak8 = (tid & 1) * 8;
    int arc = row0 + arow; if (arc >= seg_rows) arc = 0;      // clamp; invalid rows discarded in epilogue
    const __nv_bfloat16* aph = Ah + (size_t)(seg_start + arc) * K + ak8;
    const __nv_bfloat16* apl = Al + (size_t)(seg_start + arc) * K + ak8;

    // B staging (shared: planes via cp.async)
    int bpl = tid >> 6, bsub = tid & 63;
    int brow = bsub >> 3, bch = (bsub & 7) * 8;
    const __nv_bfloat16* bsrc = (bpl == 0) ? Gh : (bpl == 1) ? Gl : (bpl == 2) ? Uh : Ul;
    const __nv_bfloat16* bp0 = routed ? nullptr : bsrc + (size_t)brow * N + col0 + bch;
    const __nv_bfloat16* bp1 = routed ? nullptr : bsrc + (size_t)(brow + 8) * N + col0 + bch;

    // B staging (routed: fp32 + split)
    int bkr = tid >> 4, bcc = (tid & 15) * 4;
    const float* gp = routed ? Gf + (size_t)bkr * N + col0 + bcc : nullptr;
    const float* up = routed ? Uf + (size_t)bkr * N + col0 + bcc : nullptr;

    float accg[2][4][4] = {}, accu[2][4][4] = {};

    auto stage_async = [&](int buf, int tile) {
        cpa16(&sAh[buf][arow * LDA + ak8], aph + tile * BK);
        cpa16(&sAl[buf][arow * LDA + ak8], apl + tile * BK);
        if (!routed) {
            __nv_bfloat16* sB = (bpl == 0) ? &sGh[buf][0] : (bpl == 1) ? &sGl[buf][0]
                               : (bpl == 2) ? &sUh[buf][0] : &sUl[buf][0];
            cpa16(&sB[brow * LDB + bch], bp0 + (size_t)tile * BK * N);
            cpa16(&sB[(brow + 8) * LDB + bch], bp1 + (size_t)tile * BK * N);
        }
        cpa_commit();
    };
    auto store_routedB = [&](int buf, float4 gv, float4 uv) {
        unsigned h0, l0, h1, l1;
        int off = bkr * LDB + bcc;
        split2(gv.x, gv.y, h0, l0); split2(gv.z, gv.w, h1, l1);
        *(unsigned*)&sGh[buf][off] = h0; *(unsigned*)&sGh[buf][off + 2] = h1;
        *(unsigned*)&sGl[buf][off] = l0; *(unsigned*)&sGl[buf][off + 2] = l1;
        split2(uv.x, uv.y, h0, l0); split2(uv.z, uv.w, h1, l1);
        *(unsigned*)&sUh[buf][off] = h0; *(unsigned*)&sUh[buf][off + 2] = h1;
        *(unsigned*)&sUl[buf][off] = l0; *(unsigned*)&sUl[buf][off + 2] = l1;
    };

    auto compute = [&](int buf) {
        unsigned ah[2][4], al[2][4];
#pragma unroll
        for (int mt = 0; mt < 2; mt++) {
            int r = wm * 32 + mt * 16 + (lane & 15);
            int kk = (lane >> 4) * 8;
            ldsm4(ah[mt], &sAh[buf][r * LDA + kk]);
            ldsm4(al[mt], &sAl[buf][r * LDA + kk]);
        }
#pragma unroll
        for (int h = 0; h < 2; h++) {
            int krow = lane & 15;
            int nof = wn * 32 + h * 16 + (lane >> 4) * 8;
            unsigned gh[4], gl[4], uh[4], ul[4];
            ldsm4t(gh, &sGh[buf][krow * LDB + nof]);
            ldsm4t(gl, &sGl[buf][krow * LDB + nof]);
            ldsm4t(uh, &sUh[buf][krow * LDB + nof]);
            ldsm4t(ul, &sUl[buf][krow * LDB + nof]);
#pragma unroll
            for (int mt = 0; mt < 2; mt++)
#pragma unroll
                for (int nn = 0; nn < 2; nn++) {
                    float* cg = accg[mt][h * 2 + nn];
                    float* cu = accu[mt][h * 2 + nn];
                    mma_bf16(cg, ah[mt], gh[2*nn], gh[2*nn+1]);
                    mma_bf16(cg, ah[mt], gl[2*nn], gl[2*nn+1]);
                    mma_bf16(cg, al[mt], gh[2*nn], gh[2*nn+1]);
                    mma_bf16(cu, ah[mt], uh[2*nn], uh[2*nn+1]);
                    mma_bf16(cu, ah[mt], ul[2*nn], ul[2*nn+1]);
                    mma_bf16(cu, al[mt], uh[2*nn], uh[2*nn+1]);
                }
        }
    };

    const int nT = K / BK;
    // prologue: tile 0
    stage_async(0, 0);
    if (routed) {
        float4 gv = *(const float4*)gp, uv = *(const float4*)up;
        store_routedB(0, gv, uv);
    }
    cpa_wait_all();
    __syncthreads();

    for (int t = 0; t < nT; t++) {
        int buf = t & 1;
        bool more = (t + 1) < nT;
        float4 gv, uv;
        if (more) {
            stage_async(buf ^ 1, t + 1);
            if (routed) {
                gv = *(const float4*)(gp + (size_t)(t + 1) * BK * N);
                uv = *(const float4*)(up + (size_t)(t + 1) * BK * N);
            }
        }
        compute(buf);
        if (more) {
            if (routed) store_routedB(buf ^ 1, gv, uv);
            cpa_wait_all();
        }
        __syncthreads();
    }

    // epilogue: H = silu(g)*u -> bf16 planes
    __nv_bfloat16* Hhs = Hh + (size_t)seg_start * N;
    __nv_bfloat16* Hls = Hl + (size_t)seg_start * N;
#pragma unroll
    for (int mt = 0; mt < 2; mt++)
#pragma unroll
        for (int nn = 0; nn < 4; nn++) {
            int r0 = row0 + wm * 32 + mt * 16 + (lane >> 2);
            int c = col0 + wn * 32 + nn * 8 + (lane & 3) * 2;
            float* cg = accg[mt][nn]; float* cu = accu[mt][nn];
            if (r0 < seg_rows) {
                unsigned h, l;
                split2(silu_f(cg[0]) * cu[0], silu_f(cg[1]) * cu[1], h, l);
                ((unsigned*)Hhs)[((size_t)r0 * N + c) >> 1] = h;
                ((unsigned*)Hls)[((size_t)r0 * N + c) >> 1] = l;
            }
            int r1 = r0 + 8;
            if (r1 < seg_rows) {
                unsigned h, l;
                split2(silu_f(cg[2]) * cu[2], silu_f(cg[3]) * cu[3], h, l);
                ((unsigned*)Hhs)[((size_t)r1 * N + c) >> 1] = h;
                ((unsigned*)Hls)[((size_t)r1 * N + c) >> 1] = l;
            }
        }
}

// ================= down GEMM: cp.async planes for A (+B shared); in-kernel split for routed B =================
__global__ void __launch_bounds__(256, 2)
gemm_down_all(float* __restrict__ out, const float* __restrict__ w_down) {
    const int BM = 128, BK = 16;
    const int LDA = 24, LDB = 136;
    const int K = F_DIM, N = D_DIM;

    int z = blockIdx.z;
    bool routed = (z > 0);
    int e = z - 1;
    int seg_start = 0, seg_rows = T_TOK;
    const __nv_bfloat16 *Ah, *Al;
    const __nv_bfloat16 *Bh = nullptr, *Bl = nullptr;
    const float* Bf = nullptr;
    if (routed) {
        seg_start = g_offs[e]; seg_rows = g_offs[e + 1] - seg_start;
        Ah = g_H2h; Al = g_H2l;
        Bf = w_down + (size_t)e * F_DIM * D_DIM;
    } else {
        Ah = g_Hh; Al = g_Hl; Bh = g_sWdh; Bl = g_sWdl;
    }
    int row0 = blockIdx.y * BM;
    if (row0 >= seg_rows) return;
    int col0 = blockIdx.x * 128;

    __shared__ __align__(16) __nv_bfloat16 sAh[2][BM * LDA], sAl[2][BM * LDA];
    __shared__ __align__(16) __nv_bfloat16 sBh[2][BK * LDB], sBl[2][BK * LDB];

    int tid = threadIdx.x, lane = tid & 31, wid = tid >> 5;
    int wm = wid & 3, wn = wid >> 2;

    int arow = tid >> 1, ak8 = (tid & 1) * 8;
    int arc = row0 + arow; if (arc >= seg_rows) arc = 0;
    const __nv_bfloat16* aph = Ah + (size_t)(seg_start + arc) * K + ak8;
    const __nv_bfloat16* apl = Al + (size_t)(seg_start + arc) * K + ak8;

    // shared B planes
    int bpl = tid >> 7, bsub = tid & 127;
    int brow = bsub >> 4, bch = (bsub & 15) * 8;
    const __nv_bfloat16* bsrc = bpl ? Bl : Bh;
    const __nv_bfloat16* bp0 = routed ? nullptr : bsrc + (size_t)brow * N + col0 + bch;
    const __nv_bfloat16* bp1 = routed ? nullptr : bsrc + (size_t)(brow + 8) * N + col0 + bch;

    // routed B fp32: 2 float4 per thread
    int bkr[2], bcc[2]; const float* bp[2] = { nullptr, nullptr };
#pragma unroll
    for (int i = 0; i < 2; i++) {
        int f4 = i * 256 + tid;
        bkr[i] = f4 >> 5; bcc[i] = (f4 & 31) * 4;
        if (routed) bp[i] = Bf + (size_t)bkr[i] * N + col0 + bcc[i];
    }

    float acc[2][8][4] = {};

    auto stage_async = [&](int buf, int tile) {
        cpa16(&sAh[buf][arow * LDA + ak8], aph + tile * BK);
        cpa16(&sAl[buf][arow * LDA + ak8], apl + tile * BK);
        if (!routed) {
            __nv_bfloat16* sB = bpl ? &sBl[buf][0] : &sBh[buf][0];
            cpa16(&sB[brow * LDB + bch], bp0 + (size_t)tile * BK * N);
            cpa16(&sB[(brow + 8) * LDB + bch], bp1 + (size_t)tile * BK * N);
        }
        cpa_commit();
    };
    auto store_routedB = [&](int buf, const float4 bv[2]) {
#pragma unroll
        for (int i = 0; i < 2; i++) {
            unsigned h0, l0, h1, l1;
            split2(bv[i].x, bv[i].y, h0, l0); split2(bv[i].z, bv[i].w, h1, l1);
            int off = bkr[i] * LDB + bcc[i];
            *(unsigned*)&sBh[buf][off] = h0; *(unsigned*)&sBh[buf][off + 2] = h1;
            *(unsigned*)&sBl[buf][off] = l0; *(unsigned*)&sBl[buf][off + 2] = l1;
        }
    };

    auto compute = [&](int buf) {
        unsigned ah[2][4], al[2][4];
#pragma unroll
        for (int mt = 0; mt < 2; mt++) {
            int r = wm * 32 + mt * 16 + (lane & 15);
            int kk = (lane >> 4) * 8;
            ldsm4(ah[mt], &sAh[buf][r * LDA + kk]);
            ldsm4(al[mt], &sAl[buf][r * LDA + kk]);
        }
#pragma unroll
        for (int h = 0; h < 4; h++) {
            int krow = lane & 15;
            int nof = wn * 64 + h * 16 + (lane >> 4) * 8;
            unsigned bh[4], bl[4];
            ldsm4t(bh, &sBh[buf][krow * LDB + nof]);
            ldsm4t(bl, &sBl[buf][krow * LDB + nof]);
#pragma unroll
            for (int mt = 0; mt < 2; mt++)
#pragma unroll
                for (int nn = 0; nn < 2; nn++) {
                    float* c = acc[mt][h * 2 + nn];
                    mma_bf16(c, ah[mt], bh[2*nn], bh[2*nn+1]);
                    mma_bf16(c, ah[mt], bl[2*nn], bl[2*nn+1]);
                    mma_bf16(c, al[mt], bh[2*nn], bh[2*nn+1]);
                }
        }
    };

    const int nT = K / BK;
    stage_async(0, 0);
    if (routed) {
        float4 bv[2] = { *(const float4*)bp[0], *(const float4*)bp[1] };
        store_routedB(0, bv);
    }
    cpa_wait_all();
    __syncthreads();

    for (int t = 0; t < nT; t++) {
        int buf = t & 1;
        bool more = (t + 1) < nT;
        float4 bv[2];
        if (more) {
            stage_async(buf ^ 1, t + 1);
            if (routed) {
                bv[0] = *(const float4*)(bp[0] + (size_t)(t + 1) * BK * N);
                bv[1] = *(const float4*)(bp[1] + (size_t)(t + 1) * BK * N);
            }
        }
        compute(buf);
        if (more) {
            if (routed) store_routedB(buf ^ 1, bv);
            cpa_wait_all();
        }
        __syncthreads();
    }

#pragma unroll
    for (int mt = 0; mt < 2; mt++) {
        int rb0 = row0 + wm * 32 + mt * 16 + (lane >> 2);
        int rb1 = rb0 + 8;
        int tok0 = -1, tok1 = -1;
        if (rb0 < seg_rows) tok0 = routed ? g_order[seg_start + rb0] : rb0;
        if (rb1 < seg_rows) tok1 = routed ? g_order[seg_start + rb1] : rb1;
        float* dst = routed ? g_O2 : out;
#pragma unroll
        for (int nn = 0; nn < 8; nn++) {
            int c = col0 + wn * 64 + nn * 8 + (lane & 3) * 2;
            float* cc = acc[mt][nn];
            if (tok0 >= 0) { float2 v = { cc[0], cc[1] }; *(float2*)&dst[(size_t)tok0 * N + c] = v; }
            if (tok1 >= 0) { float2 v = { cc[2], cc[3] }; *(float2*)&dst[(size_t)tok1 * N + c] = v; }
        }
    }
}

// ---------------- final add ----------------
__global__ void add_kernel(float* __restrict__ out) {
    size_t i = (size_t)blockIdx.x * 256 + threadIdx.x;
    float4 v = ((float4*)out)[i];
    float4 w = ((const float4*)g_O2)[i];
    v.x += w.x; v.y += w.y; v.z += w.z; v.w += w.w;
    ((float4*)out)[i] = v;
}

extern "C" void kernel_launch(void* const* d_in, const int* in_sizes, int n_in,
                              void* d_out, int out_size) {
    const float* hidden   = (const float*)d_in[0];
    const float* router_w = (const float*)d_in[1];
    const float* w_gate   = (const float*)d_in[2];
    const float* w_up     = (const float*)d_in[3];
    const float* w_down   = (const float*)d_in[4];
    const float* ws_gate  = (const float*)d_in[5];
    const float* ws_up    = (const float*)d_in[6];
    const float* ws_down  = (const float*)d_in[7];
    float* out = (float*)d_out;

    conv_shared<<<512, 256>>>(ws_gate, ws_up, ws_down);
    router_kernel<<<T_TOK, 256>>>(hidden, router_w);
    rank_kernel<<<T_TOK / 256, 256>>>();
    scatter_convert<<<T_TOK, 256>>>(hidden);

    dim3 gridGU(F_DIM / 64, T_TOK / 128, NE + 1);
    gemm_gateup_all<<<gridGU, 256>>>(w_gate, w_up);
    dim3 gridDN(D_DIM / 128, T_TOK / 128, NE + 1);
    gemm_down_all<<<gridDN, 256>>>(out, w_down);
    add_kernel<<<(T_TOK * D_DIM / 4) / 256, 256>>>(out);

    (void)in_sizes; (void)n_in; (void)out_size;
}